// round 17
// baseline (speedup 1.0000x reference)
#include <cuda_runtime.h>
#include <cuda_bf16.h>
#include <cstdint>

#define NPX 1024
#define NE 1984
#define KTOP 256
#define NIMG 24
#define SINK_ITERS 150
#define EXIT_TOL 1e-2f
#define MIN_ITERS 20
#define ESTRIDE 264            // bf16 elems per row (528B)

__device__ float g_v[NIMG][NPX];
__device__ float g_bd[NIMG][2][2][KTOP];
__device__ float g_wpart[NIMG];
__device__ int g_ctr;

__device__ __forceinline__ unsigned ordf(float f) {
    unsigned u = __float_as_uint(f);
    return (u & 0x80000000u) ? ~u : (u | 0x80000000u);
}

__device__ __forceinline__ float blkMax(float v, float* r8) {
    #pragma unroll
    for (int o = 16; o; o >>= 1) v = fmaxf(v, __shfl_xor_sync(0xffffffffu, v, o));
    if ((threadIdx.x & 31) == 0) r8[threadIdx.x >> 5] = v;
    __syncthreads();
    float m = r8[0];
    #pragma unroll
    for (int k = 1; k < 8; ++k) m = fmaxf(m, r8[k]);
    __syncthreads();
    return m;
}
__device__ __forceinline__ float blkSum(float v, float* r8) {
    #pragma unroll
    for (int o = 16; o; o >>= 1) v += __shfl_xor_sync(0xffffffffu, v, o);
    if ((threadIdx.x & 31) == 0) r8[threadIdx.x >> 5] = v;
    __syncthreads();
    float s = r8[0];
    #pragma unroll
    for (int k = 1; k < 8; ++k) s += r8[k];
    __syncthreads();
    return s;
}

__device__ __forceinline__ void edge_uv(int e, int& u, int& v) {
    if (e < 992) { int rr = e / 31, cc = e - rr * 31; u = rr * 32 + cc; v = u + 1; }
    else { u = e - 992; v = u + 32; }
}

__device__ void bitonic2048(unsigned long long* keys) {
    int tid = threadIdx.x;
    for (unsigned k = 2; k <= 2048; k <<= 1)
        for (unsigned j = k >> 1; j > 0; j >>= 1) {
            __syncthreads();
            for (unsigned i = tid; i < 2048; i += 256) {
                unsigned l = i ^ j;
                if (l > i) {
                    unsigned long long a = keys[i], b = keys[l];
                    bool up = ((i & k) == 0);
                    if ((a > b) == up) { keys[i] = b; keys[l] = a; }
                }
            }
        }
    __syncthreads();
}

// ---------------- stage 1: softmax + one-hot + pool ----------------
__global__ void pool_kernel(const float* __restrict__ x, const int* __restrict__ y) {
    int idx = blockIdx.x * blockDim.x + threadIdx.x;
    if (idx >= NIMG * NPX) return;
    int m = idx >> 10, cell = idx & 1023;
    int gi = cell >> 5, gj = cell & 31;
    float acc = 0.f;
    if (m < 12) {
        int b = m / 3, c = m % 3 + 1;
        const float* xb = x + (size_t)b * 4 * 65536;
        for (int pi = 0; pi < 8; ++pi) {
            int off0 = (gi * 8 + pi) * 256 + gj * 8;
            #pragma unroll
            for (int h = 0; h < 2; ++h) {
                int off = off0 + h * 4;
                float4 v0 = *(const float4*)(xb + off);
                float4 v1 = *(const float4*)(xb + 65536 + off);
                float4 v2 = *(const float4*)(xb + 131072 + off);
                float4 v3 = *(const float4*)(xb + 196608 + off);
                const float* p0 = &v0.x; const float* p1 = &v1.x;
                const float* p2 = &v2.x; const float* p3 = &v3.x;
                #pragma unroll
                for (int j = 0; j < 4; ++j) {
                    float x0 = p0[j], x1 = p1[j], x2 = p2[j], x3 = p3[j];
                    float mx = fmaxf(fmaxf(x0, x1), fmaxf(x2, x3));
                    float e0 = __expf(x0 - mx), e1 = __expf(x1 - mx),
                          e2 = __expf(x2 - mx), e3 = __expf(x3 - mx);
                    float ec = (c == 1) ? e1 : ((c == 2) ? e2 : e3);
                    acc += ec / (e0 + e1 + e2 + e3);
                }
            }
        }
    } else {
        int mm = m - 12, b = mm / 3, c = mm % 3 + 1;
        const int* yb = y + (size_t)b * 65536;
        int cnt = 0;
        for (int pi = 0; pi < 8; ++pi) {
            int off0 = (gi * 8 + pi) * 256 + gj * 8;
            #pragma unroll
            for (int h = 0; h < 2; ++h) {
                int4 yv = *(const int4*)(yb + off0 + h * 4);
                cnt += (yv.x == c) + (yv.y == c) + (yv.z == c) + (yv.w == c);
            }
        }
        acc = (float)cnt;
    }
    g_v[m][cell] = acc * 0.015625f;
}

// ---------------- stage 2: persistence diagrams ----------------
__global__ void diagram_kernel() {
    int m = blockIdx.x >> 1;
    int r = blockIdx.x & 1;
    __shared__ float v[NPX];
    __shared__ unsigned long long keys[2048];
    __shared__ float bArr[2048], dArr[2048];
    __shared__ int parent[NPX];
    __shared__ float r8[8];
    __shared__ int2 sR[32];
    __shared__ float2 sB[32];
    __shared__ float sW[32];
    int tid = threadIdx.x;

    for (int i = tid; i < NPX; i += 256) {
        float val = g_v[m][i];
        if (r) val = -val;
        v[i] = val; parent[i] = i;
    }
    __syncthreads();

    for (int e = tid; e < 2048; e += 256) {
        unsigned long long key = ~0ULL;
        if (e < NE) {
            int u, w2; edge_uv(e, u, w2);
            float w = fmaxf(v[u], v[w2]);
            key = ((unsigned long long)ordf(w) << 32) | (unsigned)e;
        }
        keys[e] = key;
    }
    float mn = v[tid], mx = v[tid];
    for (int i = tid + 256; i < NPX; i += 256) { mn = fminf(mn, v[i]); mx = fmaxf(mx, v[i]); }

    bitonic2048(keys);
    float vmax = blkMax(mx, r8);
    float vmin = -blkMax(-mn, r8);

    if (tid < 32) {
        for (int base = 0; base < NE; base += 32) {
            int s = base + tid;
            int e = (int)(unsigned)keys[s];
            int u, vv; edge_uv(e, u, vv);
            float w = fmaxf(v[u], v[vv]);
            int ru = u;
            for (;;) { int p = parent[ru]; if (p == ru) break;
                       int g2 = parent[p]; parent[ru] = g2; ru = g2; }
            int rv = vv;
            for (;;) { int p = parent[rv]; if (p == rv) break;
                       int g2 = parent[p]; parent[rv] = g2; rv = g2; }
            sR[tid] = make_int2(ru, rv);
            sB[tid] = make_float2(v[ru], v[rv]);
            sW[tid] = w;
            __syncwarp();
            if (tid == 0) {
                #pragma unroll 4
                for (int l = 0; l < 32; ++l) {
                    int2 rr2 = sR[l];
                    float wl = sW[l];
                    float b, d;
                    if (rr2.x == rr2.y) { b = wl; d = wl; }
                    else {
                        int ra = rr2.x, rb = rr2.y;
                        float2 bb0 = sB[l];
                        float ba = bb0.x, bb2 = bb0.y;
                        int pa = parent[ra];
                        int pb2 = parent[rb];
                        if (pa != ra) {
                            do { ra = pa; pa = parent[ra]; } while (pa != ra);
                            ba = v[ra];
                        }
                        if (pb2 != rb) {
                            do { rb = pb2; pb2 = parent[rb]; } while (pb2 != rb);
                            bb2 = v[rb];
                        }
                        if (ra == rb) { b = wl; d = wl; }
                        else {
                            b = fmaxf(ba, bb2); d = wl;
                            if (ba <= bb2) parent[rb] = ra;
                            else           parent[ra] = rb;
                        }
                    }
                    bArr[base + l] = b; dArr[base + l] = d;
                }
            }
            __syncwarp();
        }
        if (tid == 0 && r == 0) { bArr[NE] = vmin; dArr[NE] = vmax; }
    }
    __syncthreads();

    int limit = (r == 0) ? NE + 1 : NE;
    for (int e = tid; e < 2048; e += 256) {
        unsigned long long key = ~0ULL;
        if (e < limit) {
            float pval = dArr[e] - bArr[e];
            key = ((unsigned long long)(~ordf(pval)) << 32) | (unsigned)e;
        }
        keys[e] = key;
    }
    bitonic2048(keys);

    if (tid < KTOP) {
        int s = (int)(unsigned)keys[tid];
        if (r == 0) {
            g_bd[m][0][0][tid] = bArr[s];
            g_bd[m][0][1][tid] = dArr[s];
        } else {
            g_bd[m][1][0][tid] = -dArr[s];
            g_bd[m][1][1][tid] = -bArr[s];
        }
    }
}

// ---------------- stage 3: single-CTA Sinkhorn (no cluster) ----------------
#define OFF_EG  0
#define OFF_EF  256
#define OFF_FS  512
#define OFF_GS  768
#define OFF_EDA 1024
#define OFF_EDB 1280
#define OFF_DAS 1536
#define OFF_DBS 1792
#define OFF_A   2048           // float2[256]
#define OFF_B   2560
#define OFF_PS  3072           // psum [8][256]
#define OFF_RED 5120
#define OFF_RED2 5128
#define OFF_SC  5136           // [0]=F2 [1]=G2 [2]=EF2w [3]=EG2w
#define EXTRA_FLOATS 5140
#define EBF_FLOATS (256 * ESTRIDE / 2)
#define SINK_SMEM_BYTES ((EBF_FLOATS + EXTRA_FLOATS) * 4)

__global__ void __launch_bounds__(256, 1)
sinkhorn_kernel(float* __restrict__ out) {
    extern __shared__ float sm[];
    __nv_bfloat162* Ebf2 = (__nv_bfloat162*)sm;        // [256][132] bf162
    float* base = sm + EBF_FLOATS;
    float* EG = base + OFF_EG;
    float* EF = base + OFF_EF;
    float* Fs = base + OFF_FS;
    float* Gs = base + OFF_GS;
    float* EDA = base + OFF_EDA;
    float* EDB = base + OFF_EDB;
    float* das = base + OFF_DAS;
    float* dbs = base + OFF_DBS;
    float2* Ash = (float2*)(base + OFF_A);
    float2* Bsh = (float2*)(base + OFF_B);
    float* psum = base + OFF_PS;
    float* r8 = base + OFF_RED;
    float* r8d = base + OFF_RED2;
    float* sc = base + OFF_SC;

    int t = threadIdx.x;
    int w = t >> 5, l = t & 31;
    int p = blockIdx.x;
    int dim = (p < 12) ? 0 : 1;
    int img = (p < 12) ? p : p - 12;

    float ab = g_bd[img][dim][0][t],      ad = g_bd[img][dim][1][t];
    float bb = g_bd[12 + img][dim][0][t], bd = g_bd[12 + img][dim][1][t];
    float2 a = make_float2(ab, ad), b = make_float2(bb, bd);
    Ash[t] = a; Bsh[t] = b;
    float da = 0.5f * (ad - ab), db = 0.5f * (bd - bb);
    EG[t] = 1.f;
    if (t < 4) sc[t] = (t < 2) ? 0.f : 1.f;
    __syncthreads();

    float mC = fmaxf(da, db);
    #pragma unroll 4
    for (int i = 0; i < KTOP; ++i) {
        float2 aq = Ash[i];
        mC = fmaxf(mC, fmaxf(fabsf(aq.x - b.x), fabsf(aq.y - b.y)));
    }
    float eps = 0.02f * fmaxf(blkMax(mC, r8), 1e-6f);
    float ie = 1.f / eps;
    das[t] = da * ie; dbs[t] = db * ie;
    EDA[t] = __expf(-da * ie); EDB[t] = __expf(-db * ie);

    // fill E row t (bf162 pairs)
    {
        __nv_bfloat162* row = Ebf2 + t * (ESTRIDE / 2);
        #pragma unroll 4
        for (int j = 0; j < 256; j += 2) {
            float2 b0 = Bsh[j], b1 = Bsh[j + 1];
            float e0 = __expf(-fmaxf(fabsf(a.x - b0.x), fabsf(a.y - b0.y)) * ie);
            float e1 = __expf(-fmaxf(fabsf(a.x - b1.x), fabsf(a.y - b1.y)) * ie);
            row[j >> 1] = __floats2bfloat162_rn(e0, e1);
        }
    }
    __syncthreads();

    const uint4* Erow = (const uint4*)(Ebf2 + t * (ESTRIDE / 2));   // 32 x 16B
    const float4* EGv = (const float4*)EG;
    float K_G = 0.f, K_F = 0.f;
    float gOld = 0.f, phiF = 0.f, phiG = 0.f;
    float myEDA = EDA[t], myEDB = EDB[t];

    for (int it = 0; it < SINK_ITERS; ++it) {
        bool doK = (it < 16) || ((it & 3) == 0);

        // ---- f-step: thread t = row t ----
        float4 acc = make_float4(0.f, 0.f, 0.f, 0.f);
        #pragma unroll
        for (int k = 0; k < 32; ++k) {
            uint4 e4 = Erow[k];
            float4 g0 = EGv[2 * k], g1 = EGv[2 * k + 1];
            float2 f0 = __bfloat1622float2(*(__nv_bfloat162*)&e4.x);
            float2 f1 = __bfloat1622float2(*(__nv_bfloat162*)&e4.y);
            float2 f2 = __bfloat1622float2(*(__nv_bfloat162*)&e4.z);
            float2 f3 = __bfloat1622float2(*(__nv_bfloat162*)&e4.w);
            acc.x = fmaf(f0.x, g0.x, acc.x); acc.y = fmaf(f0.y, g0.y, acc.y);
            acc.z = fmaf(f1.x, g0.z, acc.z); acc.w = fmaf(f1.y, g0.w, acc.w);
            acc.x = fmaf(f2.x, g1.x, acc.x); acc.y = fmaf(f2.y, g1.y, acc.y);
            acc.z = fmaf(f3.x, g1.z, acc.z); acc.w = fmaf(f3.y, g1.w, acc.w);
        }
        float s = (acc.x + acc.y) + (acc.z + acc.w);
        if (t < 32) {                          // F2 from EG/EDB
            float s2 = 0.f;
            #pragma unroll
            for (int k = 0; k < 8; ++k) { int j = t + k * 32; s2 = fmaf(EG[j], EDB[j], s2); }
            #pragma unroll
            for (int o = 16; o; o >>= 1) s2 += __shfl_xor_sync(0xffffffffu, s2, o);
            if (t == 0) sc[0] = -(K_G + __logf(s2 + 256.f * sc[3]));
        }
        float S = s + 256.f * sc[3] * myEDA;
        phiF = -(K_G + __logf(S));
        if (doK) {
            float m2 = phiF;
            #pragma unroll
            for (int o = 16; o; o >>= 1) m2 = fmaxf(m2, __shfl_xor_sync(0xffffffffu, m2, o));
            if ((t & 31) == 0) r8[w] = m2;
            __syncthreads();
            K_F = r8[0];
            #pragma unroll
            for (int k = 1; k < 8; ++k) K_F = fmaxf(K_F, r8[k]);
        }
        EF[t] = __expf(phiF - K_F);
        if (t == 0) sc[2] = __expf(sc[0] - K_F);
        __syncthreads();                       // S1: EF, sc[2] visible

        // ---- g-step: warp w = rows [32w,32w+32), lane l = cols [8l,8l+8) ----
        float a0 = 0.f, a1 = 0.f, a2 = 0.f, a3 = 0.f,
              a4 = 0.f, a5 = 0.f, a6 = 0.f, a7 = 0.f;
        {
            int rbase = w * 32;
            const uint4* Eg4 = (const uint4*)(Ebf2 + rbase * (ESTRIDE / 2)) + l;  // 16B per lane
            #pragma unroll 4
            for (int r = 0; r < 32; ++r) {
                float efi = EF[rbase + r];
                uint4 e4 = Eg4[r * (ESTRIDE / 8)];     // row stride = 33 uint4
                float2 f0 = __bfloat1622float2(*(__nv_bfloat162*)&e4.x);
                float2 f1 = __bfloat1622float2(*(__nv_bfloat162*)&e4.y);
                float2 f2 = __bfloat1622float2(*(__nv_bfloat162*)&e4.z);
                float2 f3 = __bfloat1622float2(*(__nv_bfloat162*)&e4.w);
                a0 = fmaf(efi, f0.x, a0); a1 = fmaf(efi, f0.y, a1);
                a2 = fmaf(efi, f1.x, a2); a3 = fmaf(efi, f1.y, a3);
                a4 = fmaf(efi, f2.x, a4); a5 = fmaf(efi, f2.y, a5);
                a6 = fmaf(efi, f3.x, a6); a7 = fmaf(efi, f3.y, a7);
            }
            float* ps = psum + w * 256 + l * 8;
            *(float4*)ps = make_float4(a0, a1, a2, a3);
            *(float4*)(ps + 4) = make_float4(a4, a5, a6, a7);
        }
        float g2p = 0.f;
        if (t < 32) {                          // G2 partial sums over EF
            #pragma unroll
            for (int k = 0; k < 8; ++k) { int i = t + k * 32; g2p = fmaf(EF[i], EDA[i], g2p); }
            #pragma unroll
            for (int o = 16; o; o >>= 1) g2p += __shfl_xor_sync(0xffffffffu, g2p, o);
        }
        __syncthreads();                       // S2: psum visible
        {
            float sg = ((psum[t] + psum[256 + t]) + (psum[512 + t] + psum[768 + t]))
                     + ((psum[1024 + t] + psum[1280 + t]) + (psum[1536 + t] + psum[1792 + t]));
            float Sg = sg + 256.f * sc[2] * myEDB;
            phiG = -(K_F + __logf(Sg));
        }
        if (t == 0) sc[1] = -(K_F + __logf(g2p + 256.f * sc[2]));
        float maxd = 1e30f;
        if (doK) {
            float dlt = fabsf(phiG - gOld);
            gOld = phiG;
            float m2 = phiG;
            #pragma unroll
            for (int o = 16; o; o >>= 1) {
                m2 = fmaxf(m2, __shfl_xor_sync(0xffffffffu, m2, o));
                dlt = fmaxf(dlt, __shfl_xor_sync(0xffffffffu, dlt, o));
            }
            if ((t & 31) == 0) { r8[w] = m2; r8d[w] = dlt; }
            __syncthreads();
            K_G = r8[0]; maxd = r8d[0];
            #pragma unroll
            for (int k = 1; k < 8; ++k) {
                K_G = fmaxf(K_G, r8[k]);
                maxd = fmaxf(maxd, r8d[k]);
            }
        }
        EG[t] = __expf(phiG - K_G);
        if (t == 0) sc[3] = __expf(sc[1] - K_G);
        __syncthreads();                       // S3: EG, sc[3], sc[1] visible
        if (doK && it >= MIN_ITERS && maxd < EXIT_TOL) break;
    }

    Fs[t] = phiF; Gs[t] = phiG;
    __syncthreads();

    // ---- final cost: thread t = column t over all 256 rows + rank-1 terms ----
    float acc2 = 0.f;
    #pragma unroll 4
    for (int i = 0; i < KTOP; ++i) {
        float2 aq = Ash[i];
        float cs = fmaxf(fabsf(aq.x - b.x), fabsf(aq.y - b.y)) * ie;
        acc2 += __expf(Fs[i] + phiG - cs) * cs;
    }
    acc2 += 256.f * __expf(Fs[t] + sc[1] - das[t]) * das[t];
    acc2 += 256.f * __expf(sc[0] + Gs[t] - dbs[t]) * dbs[t];
    float tot = blkSum(acc2, r8);

    if (t == 0) {
        g_wpart[p] = tot * eps;
        __threadfence();
        int ticket = atomicAdd(&g_ctr, 1);
        if (ticket == NIMG - 1) {
            g_ctr = 0;
            float ssum = 0.f;
            for (int pp = 0; pp < NIMG; ++pp) ssum += g_wpart[pp];
            out[0] = ssum * 0.25f;
        }
    }
}

extern "C" void kernel_launch(void* const* d_in, const int* in_sizes, int n_in,
                              void* d_out, int out_size) {
    (void)in_sizes; (void)n_in; (void)out_size;
    const float* x = (const float*)d_in[0];
    const int* y = (const int*)d_in[1];
    static bool attr_set = false;
    if (!attr_set) {
        cudaFuncSetAttribute(sinkhorn_kernel,
                             cudaFuncAttributeMaxDynamicSharedMemorySize,
                             SINK_SMEM_BYTES);
        attr_set = true;
    }
    pool_kernel<<<(NIMG * NPX + 255) / 256, 256>>>(x, y);
    diagram_kernel<<<48, 256>>>();
    sinkhorn_kernel<<<NIMG, 256, SINK_SMEM_BYTES>>>((float*)d_out);
}